// round 14
// baseline (speedup 1.0000x reference)
#include <cuda_runtime.h>
#include <cuda_fp16.h>
#include <cstdint>

#define DEVINL __device__ __forceinline__

namespace {
constexpr int Sn  = 1024;
constexpr int Vn  = 300;
constexpr int PRE = 300;
constexpr int FLG = 16;
constexpr int KQn = 316;
constexpr int RD  = 200;
constexpr int BSn = 32768;            // B*S

// block 128 rows x (NI*16) cols, 8 warps (4x2), warp tile 32x(NI*8), K chunk 32
constexpr int BM = 128;
constexpr int A_STAGE = BM * 48 * 2;        // 12288 B (128 rows x 96B)
constexpr int B_STAGEB = 112 * 48 * 2;      // 10752 B (<=112 rows x 96B)
constexpr int STAGE_B  = A_STAGE + B_STAGEB; // 23040
constexpr int AHo = 0, BHo = A_STAGE;
constexpr int NSTAGE = 3;
constexpr int SMEM_BYTES = NSTAGE * STAGE_B; // 69120

constexpr int NC1 = 10;   // GEMM1 K chunks (316 -> 320)
constexpr int NC2 = 7;    // GEMM2 K chunks (200 -> 224; last chunk 1 s-step)
constexpr int PW  = 224;  // proj padded width (k)
constexpr int RW  = 224;  // roles padded k
constexpr int RV  = 336;  // roles padded v

constexpr int PREP_MAT_N  = 224 * 80;             // 17920
constexpr int PREP_ROLE_N = 32 * RV * (RW / 4);   // 602112
constexpr int ROLE_PER_BLK = PREP_ROLE_N / 256;   // 2352
}

// fp16 global scratch (allocation-free rule; zero-initialized .bss)
__device__ __half g_ph[(size_t)BSn * PW];     // proj (cols 208-223 stay zero)
__device__ __half g_mh[224 * 320];            // matrix, transposed+padded
__device__ __half g_rh[(size_t)32 * RV * RW]; // roles, padded

// ---------------------------------------------------------------------------
DEVINL uint32_t smem_u32(const void* p) {
    uint32_t a;
    asm("{ .reg .u64 t; cvta.to.shared.u64 t, %1; cvt.u32.u64 %0, t; }"
        : "=r"(a) : "l"(p));
    return a;
}
DEVINL void cp16(uint32_t dst, const void* src) {
    asm volatile("cp.async.cg.shared.global [%0], [%1], 16;"
                 :: "r"(dst), "l"(src) : "memory");
}
DEVINL void cp_commit() { asm volatile("cp.async.commit_group;" ::: "memory"); }
DEVINL void cp_wait0()  { asm volatile("cp.async.wait_group 0;" ::: "memory"); }
DEVINL void cp_wait1()  { asm volatile("cp.async.wait_group 1;" ::: "memory"); }

DEVINL void ldsm4(uint32_t a, uint32_t& r0, uint32_t& r1, uint32_t& r2, uint32_t& r3) {
    asm volatile("ldmatrix.sync.aligned.m8n8.x4.shared.b16 {%0,%1,%2,%3}, [%4];"
                 : "=r"(r0), "=r"(r1), "=r"(r2), "=r"(r3) : "r"(a));
}
DEVINL void mma16816(float* c, const uint32_t* a, uint32_t b0, uint32_t b1) {
    asm volatile(
        "mma.sync.aligned.m16n8k16.row.col.f32.f16.f16.f32 "
        "{%0,%1,%2,%3}, {%4,%5,%6,%7}, {%8,%9}, {%0,%1,%2,%3};"
        : "+f"(c[0]), "+f"(c[1]), "+f"(c[2]), "+f"(c[3])
        : "r"(a[0]), "r"(a[1]), "r"(a[2]), "r"(a[3]), "r"(b0), "r"(b1));
}

// swizzle: flip 16B unit on (row & 4); conflict-free for row stride == 96 mod 128
DEVINL uint32_t swz(uint32_t byteoff, int row) { return byteoff ^ ((row & 4) << 2); }

DEVINL uint32_t packh(__half x, __half y) {
    return ((uint32_t)__half_as_ushort(y) << 16) | (uint32_t)__half_as_ushort(x);
}
DEVINL uint32_t pack2(float x, float y) {
    return packh(__float2half_rn(x), __float2half_rn(y));
}
DEVINL void sts2(uint32_t addr, uint32_t a, uint32_t b) {
    asm volatile("st.shared.v2.u32 [%0], {%1,%2};" :: "r"(addr), "r"(a), "r"(b) : "memory");
}

// ---------------------------------------------------------------------------
// compute one 32-k chunk: warp tile 32 x (NI*8), pure fp16
// B: ONE ldsm4 per ni covers BOTH s-steps (lanes 0-15 -> s0 cols, 16-31 -> s1)
// ---------------------------------------------------------------------------
template<int NI>
DEVINL void compute_chunk(uint32_t aB, uint32_t bB, int lane, int wm, int wn,
                          float c[2][NI][4], int scnt) {
    const int lr = lane & 15;
    uint32_t a[2][2][4];   // [s][mi]
#pragma unroll
    for (int s = 0; s < 2; ++s) if (s < scnt) {
#pragma unroll
        for (int mi = 0; mi < 2; ++mi) {
            const int row = wm * 32 + mi * 16 + lr;
            const int col = s * 16 + (lane >> 4) * 8;
            const uint32_t off = swz((uint32_t)(row * 96 + col * 2), row);
            ldsm4(aB + off, a[s][mi][0], a[s][mi][1], a[s][mi][2], a[s][mi][3]);
        }
    }
    const int bRowLane = lane & 7;
    const uint32_t bColB = (uint32_t)((lane >> 3) * 16);
#pragma unroll
    for (int ni = 0; ni < NI; ++ni) {
        const int brow = wn * (NI * 8) + ni * 8 + bRowLane;
        const uint32_t boff = swz((uint32_t)(brow * 96) + bColB, brow);
        uint32_t b[4];
        ldsm4(bB + boff, b[0], b[1], b[2], b[3]);
#pragma unroll
        for (int s = 0; s < 2; ++s) if (s < scnt) {
#pragma unroll
            for (int mi = 0; mi < 2; ++mi)
                mma16816(c[mi][ni], a[s][mi], b[2 * s], b[2 * s + 1]);
        }
    }
}

// ===========================================================================
// prep: matrix only (transposed + padded) -> fp16  (roles prep rides in gemm1)
// ===========================================================================
__global__ void prep_mat(const float* __restrict__ mat) {
    const int idx = blockIdx.x * 256 + threadIdx.x;
    if (idx >= PREP_MAT_N) return;
    const int n = idx / 80, k4 = (idx % 80) * 4;
#pragma unroll
    for (int i = 0; i < 4; ++i) {
        const int k = k4 + i;
        float v = 0.f;
        if (n < RD && k < KQn) v = mat[(size_t)k * RD + n];
        g_mh[n * 320 + k] = __float2half_rn(v);
    }
}

// ===========================================================================
// GEMM1 body: proj(f16)[BS, n0..n0+NI*16) = concat(pre,wid) @ mat
// ===========================================================================
template<int NI>
DEVINL void gemm1_body(const float* __restrict__ pre,
                       const float* __restrict__ wid,
                       uint32_t sb0, int m0, int n0,
                       int t, int lane, int wm, int wn) {
    float c[2][NI][4] = {};
    float4 ar[4];

    auto st = [&](int i) { return sb0 + (uint32_t)i * STAGE_B; };

    auto ldA = [&](int ch) {
#pragma unroll
        for (int j = 0; j < 4; ++j) {
            const int idx = t + 256 * j;
            const int row = idx >> 3, c4 = idx & 7;
            const int kg = ch * 32 + c4 * 4;
            const size_t rg = (size_t)(m0 + row);
            float4 v = make_float4(0.f, 0.f, 0.f, 0.f);
            if (kg < PRE)      v = *(const float4*)(pre + rg * PRE + kg);
            else if (kg < KQn) v = *(const float4*)(wid + rg * FLG + (kg - PRE));
            ar[j] = v;
        }
    };
    auto stA = [&](uint32_t sb) {
#pragma unroll
        for (int j = 0; j < 4; ++j) {
            const int idx = t + 256 * j;
            const int row = idx >> 3, c4 = idx & 7;
            const uint32_t off = swz((uint32_t)(row * 96 + c4 * 8), row);
            sts2(sb + AHo + off, pack2(ar[j].x, ar[j].y), pack2(ar[j].z, ar[j].w));
        }
    };
    auto issueB = [&](int ch, uint32_t sb) {
#pragma unroll
        for (int j = 0; j < 2; ++j) {
            const int idx = t + 256 * j;
            if (idx < NI * 64) {
                const int row = idx >> 2, c16 = idx & 3;
                const __half* src = g_mh + (size_t)(n0 + row) * 320 + ch * 32 + c16 * 8;
                const uint32_t off = swz((uint32_t)(row * 96 + c16 * 16), row);
                cp16(sb + BHo + off, src);
            }
        }
    };

    ldA(0); issueB(0, st(0)); cp_commit(); stA(st(0));
    ldA(1); issueB(1, st(1)); cp_commit(); stA(st(1));

    for (int ch = 0; ch < NC1; ++ch) {
        if (ch + 1 < NC1) cp_wait1(); else cp_wait0();
        __syncthreads();
        const int pf = ch + 2;
        if (pf < NC1) { issueB(pf, st(pf % 3)); cp_commit(); ldA(pf); }
        const uint32_t cur = st(ch % 3);
        compute_chunk<NI>(cur + AHo, cur + BHo, lane, wm, wn, c, 2);
        if (pf < NC1) stA(st(pf % 3));
    }

    // epilogue: fp32 accum -> proj fp16
#pragma unroll
    for (int mi = 0; mi < 2; ++mi)
#pragma unroll
    for (int ni = 0; ni < NI; ++ni) {
        const int r0   = m0 + wm * 32 + mi * 16 + (lane >> 2);
        const int colg = n0 + wn * (NI * 8) + ni * 8 + (lane & 3) * 2;
        *reinterpret_cast<uint32_t*>(g_ph + (size_t)r0 * PW + colg)
            = pack2(c[mi][ni][0], c[mi][ni][1]);
        *reinterpret_cast<uint32_t*>(g_ph + (size_t)(r0 + 8) * PW + colg)
            = pack2(c[mi][ni][2], c[mi][ni][3]);
    }
}

// gemm1 launch carries a third y-slice that performs the roles fp32->fp16 prep
// (no dependency on gemm1 output; gemm2 launches afterward and sees it complete)
__global__ __launch_bounds__(256, 2) void gemm1(
    const float* __restrict__ pre,
    const float* __restrict__ wid,
    const float* __restrict__ roles)
{
    if (blockIdx.y == 2) {
        // distributed prep_roles: 256 blocks x 2352 items (8 halves each)
        const int base = blockIdx.x * ROLE_PER_BLK;
        for (int i = threadIdx.x; i < ROLE_PER_BLK; i += 256) {
            const int r0 = base + i;
            const int b  = r0 / (RV * (RW / 4));
            const int r  = r0 % (RV * (RW / 4));
            const int v  = r / (RW / 4);
            const int k  = (r % (RW / 4)) * 4;
            uint32_t h0 = 0, h1 = 0;
            if (v < Vn && k < RD) {
                const float4 f = *(const float4*)(roles + ((size_t)b * Vn + v) * RD + k);
                h0 = pack2(f.x, f.y);
                h1 = pack2(f.z, f.w);
            }
            const size_t off = (size_t)b * RV * RW + (size_t)v * RW + k;
            *reinterpret_cast<uint2*>(g_rh + off) = make_uint2(h0, h1);
        }
        return;
    }

    extern __shared__ __align__(128) char smraw[];
    const uint32_t sb0 = smem_u32(smraw);
    const int t = threadIdx.x, lane = t & 31, warp = t >> 5;
    const int wm = warp >> 1, wn = warp & 1;
    const int m0 = blockIdx.x * BM;
    if (blockIdx.y == 0)
        gemm1_body<7>(pre, wid, sb0, m0, 0,   t, lane, wm, wn);   // cols 0..111
    else
        gemm1_body<6>(pre, wid, sb0, m0, 112, t, lane, wm, wn);   // cols 112..207
}

// ===========================================================================
// GEMM2 body: out[r, v0..) = proj[r,:208) . roles, col v==1 zeroed
// ===========================================================================
template<int NI>
DEVINL void gemm2_body(float* __restrict__ out,
                       uint32_t sb0, int m0, int v0, int b,
                       int t, int lane, int wm, int wn) {
    float c[2][NI][4] = {};
    const size_t rbase = (size_t)b * RV * RW;

    auto st = [&](int i) { return sb0 + (uint32_t)i * STAGE_B; };

    auto issue = [&](int ch, uint32_t sb) {
        const int k0 = ch * 32;
#pragma unroll
        for (int j = 0; j < 4; ++j) {
            const int idx = t + 256 * j;
            if (idx < 512) {                        // A: proj
                const int row = idx >> 2, c16 = idx & 3;
                const __half* src = g_ph + (size_t)(m0 + row) * PW + k0 + c16 * 8;
                const uint32_t off = swz((uint32_t)(row * 96 + c16 * 16), row);
                cp16(sb + AHo + off, src);
            } else if (idx < 512 + NI * 64) {       // B: roles
                const int i2 = idx - 512;
                const int row = i2 >> 2, c16 = i2 & 3;
                const __half* src = g_rh + rbase + (size_t)(v0 + row) * RW + k0 + c16 * 8;
                const uint32_t off = swz((uint32_t)(row * 96 + c16 * 16), row);
                cp16(sb + BHo + off, src);
            }
        }
    };

    issue(0, st(0)); cp_commit();
    issue(1, st(1)); cp_commit();

    for (int ch = 0; ch < NC2; ++ch) {
        if (ch + 1 < NC2) cp_wait1(); else cp_wait0();
        __syncthreads();
        const int pf = ch + 2;
        if (pf < NC2) { issue(pf, st(pf % 3)); cp_commit(); }
        const int scnt = (ch == NC2 - 1) ? 1 : 2;   // k 208..223 is all-zero pad
        const uint32_t cur = st(ch % 3);
        compute_chunk<NI>(cur + AHo, cur + BHo, lane, wm, wn, c, scnt);
    }

    // epilogue: fp32 stores, zero global column 1
#pragma unroll
    for (int mi = 0; mi < 2; ++mi)
#pragma unroll
    for (int ni = 0; ni < NI; ++ni) {
        const int r0   = m0 + wm * 32 + mi * 16 + (lane >> 2);
        const int colg = v0 + wn * (NI * 8) + ni * 8 + (lane & 3) * 2;
        if (colg < Vn) {
            float a0 = c[mi][ni][0], a1 = c[mi][ni][1];
            float a2 = c[mi][ni][2], a3 = c[mi][ni][3];
            if (colg == 0) { a1 = 0.f; a3 = 0.f; }
            *(float2*)(out + (size_t)r0 * Vn + colg)       = make_float2(a0, a1);
            *(float2*)(out + (size_t)(r0 + 8) * Vn + colg) = make_float2(a2, a3);
        }
    }
}

__global__ __launch_bounds__(256, 2) void gemm2(float* __restrict__ out)
{
    extern __shared__ __align__(128) char smraw[];
    const uint32_t sb0 = smem_u32(smraw);
    const int t = threadIdx.x, lane = t & 31, warp = t >> 5;
    const int wm = warp >> 1, wn = warp & 1;
    const int m0 = blockIdx.x * BM;
    const int b  = blockIdx.x >> 3;           // 8 M-tiles per batch
    if (blockIdx.y < 2)
        gemm2_body<7>(out, sb0, m0, blockIdx.y * 112, b, t, lane, wm, wn);
    else
        gemm2_body<5>(out, sb0, m0, 224, b, t, lane, wm, wn);   // v 224..303
}

// ===========================================================================
// kernel_launch  (inputs: role_vectors, pretrained_emb, word_id_emb, matrix, seq_len)
// ===========================================================================
extern "C" void kernel_launch(void* const* d_in, const int* in_sizes, int n_in,
                              void* d_out, int out_size)
{
    const float* roles = (const float*)d_in[0];
    const float* pre   = (const float*)d_in[1];
    const float* wid   = (const float*)d_in[2];
    const float* mat   = (const float*)d_in[3];

    cudaFuncSetAttribute(gemm1, cudaFuncAttributeMaxDynamicSharedMemorySize, SMEM_BYTES);
    cudaFuncSetAttribute(gemm2, cudaFuncAttributeMaxDynamicSharedMemorySize, SMEM_BYTES);

    prep_mat<<<(PREP_MAT_N + 255) / 256, 256>>>(mat);
    gemm1<<<dim3(BSn / BM, 3), 256, SMEM_BYTES>>>(pre, wid, roles);
    gemm2<<<dim3(BSn / BM, 3), 256, SMEM_BYTES>>>((float*)d_out);
}

// round 15
// speedup vs baseline: 1.0336x; 1.0336x over previous
#include <cuda_runtime.h>
#include <cuda_fp16.h>
#include <cstdint>

#define DEVINL __device__ __forceinline__

namespace {
constexpr int Sn  = 1024;
constexpr int Vn  = 300;
constexpr int PRE = 300;
constexpr int FLG = 16;
constexpr int KQn = 316;
constexpr int RD  = 200;
constexpr int BSn = 32768;            // B*S

// block 128 rows x (NI*16) cols, 8 warps (4x2), warp tile 32x(NI*8), K chunk 32
constexpr int BM = 128;
constexpr int A_STAGE = BM * 48 * 2;        // 12288 B (128 rows x 96B stride)
constexpr int B_STAGEB = 112 * 48 * 2;      // 10752 B (<=112 rows x 96B)
constexpr int STAGE_B  = A_STAGE + B_STAGEB; // 23040
constexpr int AHo = 0, BHo = A_STAGE;
constexpr int NSTAGE = 4;
constexpr int SMEM_BYTES = NSTAGE * STAGE_B; // 92160

constexpr int NC1 = 10;   // GEMM1 K chunks (316 -> 320)
constexpr int NC2 = 7;    // GEMM2 K chunks (200 -> 224; last chunk 1 s-step)
constexpr int PW  = 224;  // proj padded width (k)
constexpr int RW  = 224;  // roles padded k
constexpr int RV  = 336;  // roles padded v

constexpr int PREP_MAT_N  = 224 * 80;             // 17920
constexpr int PREP_ROLE_N = 32 * RV * (RW / 4);   // 602112
constexpr int PREP_TOTAL  = PREP_MAT_N + PREP_ROLE_N;
}

// fp16 global scratch (allocation-free rule; zero-initialized .bss)
__device__ __half g_ph[(size_t)BSn * PW];     // proj (cols 208-223 stay zero)
__device__ __half g_mh[224 * 320];            // matrix, transposed+padded
__device__ __half g_rh[(size_t)32 * RV * RW]; // roles, padded

// ---------------------------------------------------------------------------
DEVINL uint32_t smem_u32(const void* p) {
    uint32_t a;
    asm("{ .reg .u64 t; cvta.to.shared.u64 t, %1; cvt.u32.u64 %0, t; }"
        : "=r"(a) : "l"(p));
    return a;
}
DEVINL void cp16(uint32_t dst, const void* src) {
    asm volatile("cp.async.cg.shared.global [%0], [%1], 16;"
                 :: "r"(dst), "l"(src) : "memory");
}
DEVINL void cp_commit() { asm volatile("cp.async.commit_group;" ::: "memory"); }
DEVINL void cp_wait0()  { asm volatile("cp.async.wait_group 0;" ::: "memory"); }
DEVINL void cp_wait1()  { asm volatile("cp.async.wait_group 1;" ::: "memory"); }
DEVINL void cp_wait2()  { asm volatile("cp.async.wait_group 2;" ::: "memory"); }

DEVINL void ldsm4(uint32_t a, uint32_t& r0, uint32_t& r1, uint32_t& r2, uint32_t& r3) {
    asm volatile("ldmatrix.sync.aligned.m8n8.x4.shared.b16 {%0,%1,%2,%3}, [%4];"
                 : "=r"(r0), "=r"(r1), "=r"(r2), "=r"(r3) : "r"(a));
}
DEVINL void mma16816(float* c, const uint32_t* a, uint32_t b0, uint32_t b1) {
    asm volatile(
        "mma.sync.aligned.m16n8k16.row.col.f32.f16.f16.f32 "
        "{%0,%1,%2,%3}, {%4,%5,%6,%7}, {%8,%9}, {%0,%1,%2,%3};"
        : "+f"(c[0]), "+f"(c[1]), "+f"(c[2]), "+f"(c[3])
        : "r"(a[0]), "r"(a[1]), "r"(a[2]), "r"(a[3]), "r"(b0), "r"(b1));
}

// swizzle: flip 16B unit on (row & 4); conflict-free for row stride == 96 mod 128
DEVINL uint32_t swz(uint32_t byteoff, int row) { return byteoff ^ ((row & 4) << 2); }

DEVINL uint32_t packh(__half x, __half y) {
    return ((uint32_t)__half_as_ushort(y) << 16) | (uint32_t)__half_as_ushort(x);
}
DEVINL uint32_t pack2(float x, float y) {
    return packh(__float2half_rn(x), __float2half_rn(y));
}
DEVINL void sts2(uint32_t addr, uint32_t a, uint32_t b) {
    asm volatile("st.shared.v2.u32 [%0], {%1,%2};" :: "r"(addr), "r"(a), "r"(b) : "memory");
}

// ---------------------------------------------------------------------------
// compute one 32-k chunk: warp tile 32 x (NI*8), pure fp16, SCNT s-steps
// B: ONE ldsm4 per ni covers BOTH s-steps (lanes 0-15 -> s0 cols, 16-31 -> s1)
// ---------------------------------------------------------------------------
template<int NI, int SCNT>
DEVINL void compute_chunk(uint32_t aB, uint32_t bB, int lane, int wm, int wn,
                          float c[2][NI][4]) {
    const int lr = lane & 15;
    uint32_t a[SCNT][2][4];   // [s][mi]
#pragma unroll
    for (int s = 0; s < SCNT; ++s) {
#pragma unroll
        for (int mi = 0; mi < 2; ++mi) {
            const int row = wm * 32 + mi * 16 + lr;
            const int col = s * 16 + (lane >> 4) * 8;
            const uint32_t off = swz((uint32_t)(row * 96 + col * 2), row);
            ldsm4(aB + off, a[s][mi][0], a[s][mi][1], a[s][mi][2], a[s][mi][3]);
        }
    }
    const int bRowLane = lane & 7;
    const uint32_t bColB = (uint32_t)((lane >> 3) * 16);
#pragma unroll
    for (int ni = 0; ni < NI; ++ni) {
        const int brow = wn * (NI * 8) + ni * 8 + bRowLane;
        const uint32_t boff = swz((uint32_t)(brow * 96) + bColB, brow);
        uint32_t b[4];
        ldsm4(bB + boff, b[0], b[1], b[2], b[3]);
#pragma unroll
        for (int s = 0; s < SCNT; ++s) {
#pragma unroll
            for (int mi = 0; mi < 2; ++mi)
                mma16816(c[mi][ni], a[s][mi], b[2 * s], b[2 * s + 1]);
        }
    }
}

// ===========================================================================
// prep (merged): matrix (transposed+padded) and roles (padded) -> fp16
// ===========================================================================
__global__ void prep_all(const float* __restrict__ mat,
                         const float* __restrict__ roles) {
    const int idx = blockIdx.x * 256 + threadIdx.x;
    if (idx < PREP_MAT_N) {
        const int n = idx / 80, k4 = (idx % 80) * 4;
#pragma unroll
        for (int i = 0; i < 4; ++i) {
            const int k = k4 + i;
            float v = 0.f;
            if (n < RD && k < KQn) v = mat[(size_t)k * RD + n];
            g_mh[n * 320 + k] = __float2half_rn(v);
        }
    } else if (idx < PREP_TOTAL) {
        const int r0 = idx - PREP_MAT_N;
        const int b  = r0 / (RV * (RW / 4));
        const int r  = r0 % (RV * (RW / 4));
        const int v  = r / (RW / 4);
        const int k  = (r % (RW / 4)) * 4;
        uint32_t h0 = 0, h1 = 0;
        if (v < Vn && k < RD) {
            const float4 f = *(const float4*)(roles + ((size_t)b * Vn + v) * RD + k);
            h0 = pack2(f.x, f.y);
            h1 = pack2(f.z, f.w);
        }
        const size_t off = (size_t)b * RV * RW + (size_t)v * RW + k;
        *reinterpret_cast<uint2*>(g_rh + off) = make_uint2(h0, h1);
    }
}

// ===========================================================================
// GEMM1 body: proj(f16)[BS, n0..n0+NI*16) = concat(pre,wid) @ mat
// 4-stage ring, prefetch distance 3
// ===========================================================================
template<int NI>
DEVINL void gemm1_body(const float* __restrict__ pre,
                       const float* __restrict__ wid,
                       uint32_t sb0, int m0, int n0,
                       int t, int lane, int wm, int wn) {
    float c[2][NI][4] = {};
    float4 ar[4];

    auto st = [&](int i) { return sb0 + (uint32_t)i * STAGE_B; };

    auto ldA = [&](int ch) {
#pragma unroll
        for (int j = 0; j < 4; ++j) {
            const int idx = t + 256 * j;
            const int row = idx >> 3, c4 = idx & 7;
            const int kg = ch * 32 + c4 * 4;
            const size_t rg = (size_t)(m0 + row);
            float4 v = make_float4(0.f, 0.f, 0.f, 0.f);
            if (kg < PRE)      v = *(const float4*)(pre + rg * PRE + kg);
            else if (kg < KQn) v = *(const float4*)(wid + rg * FLG + (kg - PRE));
            ar[j] = v;
        }
    };
    auto stA = [&](uint32_t sb) {
#pragma unroll
        for (int j = 0; j < 4; ++j) {
            const int idx = t + 256 * j;
            const int row = idx >> 3, c4 = idx & 7;
            const uint32_t off = swz((uint32_t)(row * 96 + c4 * 8), row);
            sts2(sb + AHo + off, pack2(ar[j].x, ar[j].y), pack2(ar[j].z, ar[j].w));
        }
    };
    auto issueB = [&](int ch, uint32_t sb) {
#pragma unroll
        for (int j = 0; j < 2; ++j) {
            const int idx = t + 256 * j;
            if (idx < NI * 64) {
                const int row = idx >> 2, c16 = idx & 3;
                const __half* src = g_mh + (size_t)(n0 + row) * 320 + ch * 32 + c16 * 8;
                const uint32_t off = swz((uint32_t)(row * 96 + c16 * 16), row);
                cp16(sb + BHo + off, src);
            }
        }
    };

    ldA(0); issueB(0, st(0)); cp_commit(); stA(st(0));
    ldA(1); issueB(1, st(1)); cp_commit(); stA(st(1));
    ldA(2); issueB(2, st(2)); cp_commit(); stA(st(2));

    for (int ch = 0; ch < NC1; ++ch) {
        if (ch + 2 < NC1)      cp_wait2();
        else if (ch + 1 < NC1) cp_wait1();
        else                   cp_wait0();
        __syncthreads();
        const int pf = ch + 3;
        if (pf < NC1) { issueB(pf, st(pf % NSTAGE)); cp_commit(); ldA(pf); }
        const uint32_t cur = st(ch % NSTAGE);
        compute_chunk<NI, 2>(cur + AHo, cur + BHo, lane, wm, wn, c);
        if (pf < NC1) stA(st(pf % NSTAGE));
    }

    // epilogue: fp32 accum -> proj fp16
#pragma unroll
    for (int mi = 0; mi < 2; ++mi)
#pragma unroll
    for (int ni = 0; ni < NI; ++ni) {
        const int r0   = m0 + wm * 32 + mi * 16 + (lane >> 2);
        const int colg = n0 + wn * (NI * 8) + ni * 8 + (lane & 3) * 2;
        *reinterpret_cast<uint32_t*>(g_ph + (size_t)r0 * PW + colg)
            = pack2(c[mi][ni][0], c[mi][ni][1]);
        *reinterpret_cast<uint32_t*>(g_ph + (size_t)(r0 + 8) * PW + colg)
            = pack2(c[mi][ni][2], c[mi][ni][3]);
    }
}

__global__ __launch_bounds__(256, 2) void gemm1(
    const float* __restrict__ pre,
    const float* __restrict__ wid)
{
    extern __shared__ __align__(128) char smraw[];
    const uint32_t sb0 = smem_u32(smraw);
    const int t = threadIdx.x, lane = t & 31, warp = t >> 5;
    const int wm = warp >> 1, wn = warp & 1;
    const int m0 = blockIdx.x * BM;
    if (blockIdx.y == 0)
        gemm1_body<7>(pre, wid, sb0, m0, 0,   t, lane, wm, wn);   // cols 0..111
    else
        gemm1_body<6>(pre, wid, sb0, m0, 112, t, lane, wm, wn);   // cols 112..207
}

// ===========================================================================
// GEMM2 body: out[r, v0..) = proj[r,:208) . roles, col v==1 zeroed
// 4-stage ring, prefetch distance 3; last chunk specialized SCNT=1
// ===========================================================================
template<int NI>
DEVINL void gemm2_body(float* __restrict__ out,
                       uint32_t sb0, int m0, int v0, int b,
                       int t, int lane, int wm, int wn) {
    float c[2][NI][4] = {};
    const size_t rbase = (size_t)b * RV * RW;

    auto st = [&](int i) { return sb0 + (uint32_t)i * STAGE_B; };

    auto issue = [&](int ch, uint32_t sb) {
        const int k0 = ch * 32;
#pragma unroll
        for (int j = 0; j < 4; ++j) {
            const int idx = t + 256 * j;
            if (idx < 512) {                        // A: proj
                const int row = idx >> 2, c16 = idx & 3;
                const __half* src = g_ph + (size_t)(m0 + row) * PW + k0 + c16 * 8;
                const uint32_t off = swz((uint32_t)(row * 96 + c16 * 16), row);
                cp16(sb + AHo + off, src);
            } else if (idx < 512 + NI * 64) {       // B: roles
                const int i2 = idx - 512;
                const int row = i2 >> 2, c16 = i2 & 3;
                const __half* src = g_rh + rbase + (size_t)(v0 + row) * RW + k0 + c16 * 8;
                const uint32_t off = swz((uint32_t)(row * 96 + c16 * 16), row);
                cp16(sb + BHo + off, src);
            }
        }
    };

    issue(0, st(0)); cp_commit();
    issue(1, st(1)); cp_commit();
    issue(2, st(2)); cp_commit();

    for (int ch = 0; ch < NC2; ++ch) {
        if (ch + 2 < NC2)      cp_wait2();
        else if (ch + 1 < NC2) cp_wait1();
        else                   cp_wait0();
        __syncthreads();
        const int pf = ch + 3;
        if (pf < NC2) { issue(pf, st(pf % NSTAGE)); cp_commit(); }
        const uint32_t cur = st(ch % NSTAGE);
        if (ch == NC2 - 1)   // k 208..223 is all-zero pad -> single s-step
            compute_chunk<NI, 1>(cur + AHo, cur + BHo, lane, wm, wn, c);
        else
            compute_chunk<NI, 2>(cur + AHo, cur + BHo, lane, wm, wn, c);
    }

    // epilogue: fp32 stores, zero global column 1
#pragma unroll
    for (int mi = 0; mi < 2; ++mi)
#pragma unroll
    for (int ni = 0; ni < NI; ++ni) {
        const int r0   = m0 + wm * 32 + mi * 16 + (lane >> 2);
        const int colg = v0 + wn * (NI * 8) + ni * 8 + (lane & 3) * 2;
        if (colg < Vn) {
            float a0 = c[mi][ni][0], a1 = c[mi][ni][1];
            float a2 = c[mi][ni][2], a3 = c[mi][ni][3];
            if (colg == 0) { a1 = 0.f; a3 = 0.f; }
            *(float2*)(out + (size_t)r0 * Vn + colg)       = make_float2(a0, a1);
            *(float2*)(out + (size_t)(r0 + 8) * Vn + colg) = make_float2(a2, a3);
        }
    }
}

__global__ __launch_bounds__(256, 2) void gemm2(float* __restrict__ out)
{
    extern __shared__ __align__(128) char smraw[];
    const uint32_t sb0 = smem_u32(smraw);
    const int t = threadIdx.x, lane = t & 31, warp = t >> 5;
    const int wm = warp >> 1, wn = warp & 1;
    const int m0 = blockIdx.x * BM;
    const int b  = blockIdx.x >> 3;           // 8 M-tiles per batch
    if (blockIdx.y < 2)
        gemm2_body<7>(out, sb0, m0, blockIdx.y * 112, b, t, lane, wm, wn);
    else
        gemm2_body<5>(out, sb0, m0, 224, b, t, lane, wm, wn);   // v 224..303
}

// ===========================================================================
// kernel_launch  (inputs: role_vectors, pretrained_emb, word_id_emb, matrix, seq_len)
// ===========================================================================
extern "C" void kernel_launch(void* const* d_in, const int* in_sizes, int n_in,
                              void* d_out, int out_size)
{
    const float* roles = (const float*)d_in[0];
    const float* pre   = (const float*)d_in[1];
    const float* wid   = (const float*)d_in[2];
    const float* mat   = (const float*)d_in[3];

    cudaFuncSetAttribute(gemm1, cudaFuncAttributeMaxDynamicSharedMemorySize, SMEM_BYTES);
    cudaFuncSetAttribute(gemm2, cudaFuncAttributeMaxDynamicSharedMemorySize, SMEM_BYTES);

    prep_all<<<(PREP_TOTAL + 255) / 256, 256>>>(mat, roles);
    gemm1<<<dim3(BSn / BM, 2), 256, SMEM_BYTES>>>(pre, wid);
    gemm2<<<dim3(BSn / BM, 3), 256, SMEM_BYTES>>>((float*)d_out);
}

// round 16
// speedup vs baseline: 1.0880x; 1.0526x over previous
#include <cuda_runtime.h>
#include <cuda_fp16.h>
#include <cstdint>

#define DEVINL __device__ __forceinline__

namespace {
constexpr int Sn  = 1024;
constexpr int Vn  = 300;
constexpr int PRE = 300;
constexpr int FLG = 16;
constexpr int KQn = 316;
constexpr int RD  = 200;
constexpr int BSn = 32768;            // B*S

// block 128 rows x (NI*16) cols, 8 warps (4x2), warp tile 32x(NI*8), K chunk 32
constexpr int BM = 128;
constexpr int A_STAGE = BM * 48 * 2;        // 12288 B (128 rows x 96B)
constexpr int B_STAGEB = 112 * 48 * 2;      // 10752 B (<=112 rows x 96B)
constexpr int STAGE_B  = A_STAGE + B_STAGEB; // 23040
constexpr int AHo = 0, BHo = A_STAGE;
constexpr int NSTAGE = 3;
constexpr int SMEM_BYTES = NSTAGE * STAGE_B; // 69120

constexpr int NC1 = 10;   // GEMM1 K chunks (316 -> 320)
constexpr int NC2 = 7;    // GEMM2 K chunks (200 -> 224; last chunk 1 s-step)
constexpr int PW  = 224;  // proj padded width (k)
constexpr int RW  = 224;  // roles padded k
constexpr int RV  = 336;  // roles padded v

constexpr int PREP_MAT_N  = 224 * 80;             // 17920
constexpr int PREP_ROLE_N = 32 * RV * (RW / 4);   // 602112
constexpr int PREP_TOTAL  = PREP_MAT_N + PREP_ROLE_N;

constexpr int NTILE = BSn / BM;     // 256 m-tiles
constexpr int G1_BLOCKS = 2 * NTILE;  // 512
}

// fp16 global scratch (allocation-free rule; zero-initialized .bss)
__device__ __half g_ph[(size_t)BSn * PW];     // proj (cols 208-223 stay zero)
__device__ __half g_mh[224 * 320];            // matrix, transposed+padded
__device__ __half g_rh[(size_t)32 * RV * RW]; // roles, padded
__device__ int    g_flags[NTILE];             // per-m-tile proj-ready counters

// ---------------------------------------------------------------------------
DEVINL uint32_t smem_u32(const void* p) {
    uint32_t a;
    asm("{ .reg .u64 t; cvta.to.shared.u64 t, %1; cvt.u32.u64 %0, t; }"
        : "=r"(a) : "l"(p));
    return a;
}
DEVINL void cp16(uint32_t dst, const void* src) {
    asm volatile("cp.async.cg.shared.global [%0], [%1], 16;"
                 :: "r"(dst), "l"(src) : "memory");
}
DEVINL void cp_commit() { asm volatile("cp.async.commit_group;" ::: "memory"); }
DEVINL void cp_wait0()  { asm volatile("cp.async.wait_group 0;" ::: "memory"); }
DEVINL void cp_wait1()  { asm volatile("cp.async.wait_group 1;" ::: "memory"); }

DEVINL void ldsm4(uint32_t a, uint32_t& r0, uint32_t& r1, uint32_t& r2, uint32_t& r3) {
    asm volatile("ldmatrix.sync.aligned.m8n8.x4.shared.b16 {%0,%1,%2,%3}, [%4];"
                 : "=r"(r0), "=r"(r1), "=r"(r2), "=r"(r3) : "r"(a));
}
DEVINL void mma16816(float* c, const uint32_t* a, uint32_t b0, uint32_t b1) {
    asm volatile(
        "mma.sync.aligned.m16n8k16.row.col.f32.f16.f16.f32 "
        "{%0,%1,%2,%3}, {%4,%5,%6,%7}, {%8,%9}, {%0,%1,%2,%3};"
        : "+f"(c[0]), "+f"(c[1]), "+f"(c[2]), "+f"(c[3])
        : "r"(a[0]), "r"(a[1]), "r"(a[2]), "r"(a[3]), "r"(b0), "r"(b1));
}

DEVINL int ld_acquire(const int* p) {
    int v;
    asm volatile("ld.acquire.gpu.global.b32 %0, [%1];" : "=r"(v) : "l"(p) : "memory");
    return v;
}

// swizzle: flip 16B unit on (row & 4); conflict-free for row stride == 96 mod 128
DEVINL uint32_t swz(uint32_t byteoff, int row) { return byteoff ^ ((row & 4) << 2); }

DEVINL uint32_t packh(__half x, __half y) {
    return ((uint32_t)__half_as_ushort(y) << 16) | (uint32_t)__half_as_ushort(x);
}
DEVINL uint32_t pack2(float x, float y) {
    return packh(__float2half_rn(x), __float2half_rn(y));
}
DEVINL void sts2(uint32_t addr, uint32_t a, uint32_t b) {
    asm volatile("st.shared.v2.u32 [%0], {%1,%2};" :: "r"(addr), "r"(a), "r"(b) : "memory");
}

// ---------------------------------------------------------------------------
// compute one 32-k chunk: warp tile 32 x (NI*8), pure fp16
// B: ONE ldsm4 per ni covers BOTH s-steps (lanes 0-15 -> s0 cols, 16-31 -> s1)
// ---------------------------------------------------------------------------
template<int NI>
DEVINL void compute_chunk(uint32_t aB, uint32_t bB, int lane, int wm, int wn,
                          float c[2][NI][4], int scnt) {
    const int lr = lane & 15;
    uint32_t a[2][2][4];   // [s][mi]
#pragma unroll
    for (int s = 0; s < 2; ++s) if (s < scnt) {
#pragma unroll
        for (int mi = 0; mi < 2; ++mi) {
            const int row = wm * 32 + mi * 16 + lr;
            const int col = s * 16 + (lane >> 4) * 8;
            const uint32_t off = swz((uint32_t)(row * 96 + col * 2), row);
            ldsm4(aB + off, a[s][mi][0], a[s][mi][1], a[s][mi][2], a[s][mi][3]);
        }
    }
    const int bRowLane = lane & 7;
    const uint32_t bColB = (uint32_t)((lane >> 3) * 16);
#pragma unroll
    for (int ni = 0; ni < NI; ++ni) {
        const int brow = wn * (NI * 8) + ni * 8 + bRowLane;
        const uint32_t boff = swz((uint32_t)(brow * 96) + bColB, brow);
        uint32_t b[4];
        ldsm4(bB + boff, b[0], b[1], b[2], b[3]);
#pragma unroll
        for (int s = 0; s < 2; ++s) if (s < scnt) {
#pragma unroll
            for (int mi = 0; mi < 2; ++mi)
                mma16816(c[mi][ni], a[s][mi], b[2 * s], b[2 * s + 1]);
        }
    }
}

// ===========================================================================
// prep (merged): matrix + roles -> fp16; block 0 also resets the tile flags
// ===========================================================================
__global__ void prep_all(const float* __restrict__ mat,
                         const float* __restrict__ roles) {
    if (blockIdx.x == 0 && threadIdx.x < NTILE) g_flags[threadIdx.x] = 0;
    const int idx = blockIdx.x * 256 + threadIdx.x;
    if (idx < PREP_MAT_N) {
        const int n = idx / 80, k4 = (idx % 80) * 4;
#pragma unroll
        for (int i = 0; i < 4; ++i) {
            const int k = k4 + i;
            float v = 0.f;
            if (n < RD && k < KQn) v = mat[(size_t)k * RD + n];
            g_mh[n * 320 + k] = __float2half_rn(v);
        }
    } else if (idx < PREP_TOTAL) {
        const int r0 = idx - PREP_MAT_N;
        const int b  = r0 / (RV * (RW / 4));
        const int r  = r0 % (RV * (RW / 4));
        const int v  = r / (RW / 4);
        const int k  = (r % (RW / 4)) * 4;
        uint32_t h0 = 0, h1 = 0;
        if (v < Vn && k < RD) {
            const float4 f = *(const float4*)(roles + ((size_t)b * Vn + v) * RD + k);
            h0 = pack2(f.x, f.y);
            h1 = pack2(f.z, f.w);
        }
        const size_t off = (size_t)b * RV * RW + (size_t)v * RW + k;
        *reinterpret_cast<uint2*>(g_rh + off) = make_uint2(h0, h1);
    }
}

// ===========================================================================
// GEMM1 body: proj(f16)[m-tile, n0..n0+NI*16) = concat(pre,wid) @ mat
// ===========================================================================
template<int NI>
DEVINL void gemm1_body(const float* __restrict__ pre,
                       const float* __restrict__ wid,
                       uint32_t sb0, int m0, int n0,
                       int t, int lane, int wm, int wn) {
    float c[2][NI][4] = {};
    float4 ar[4];

    auto st = [&](int i) { return sb0 + (uint32_t)i * STAGE_B; };

    auto ldA = [&](int ch) {
#pragma unroll
        for (int j = 0; j < 4; ++j) {
            const int idx = t + 256 * j;
            const int row = idx >> 3, c4 = idx & 7;
            const int kg = ch * 32 + c4 * 4;
            const size_t rg = (size_t)(m0 + row);
            float4 v = make_float4(0.f, 0.f, 0.f, 0.f);
            if (kg < PRE)      v = *(const float4*)(pre + rg * PRE + kg);
            else if (kg < KQn) v = *(const float4*)(wid + rg * FLG + (kg - PRE));
            ar[j] = v;
        }
    };
    auto stA = [&](uint32_t sb) {
#pragma unroll
        for (int j = 0; j < 4; ++j) {
            const int idx = t + 256 * j;
            const int row = idx >> 3, c4 = idx & 7;
            const uint32_t off = swz((uint32_t)(row * 96 + c4 * 8), row);
            sts2(sb + AHo + off, pack2(ar[j].x, ar[j].y), pack2(ar[j].z, ar[j].w));
        }
    };
    auto issueB = [&](int ch, uint32_t sb) {
#pragma unroll
        for (int j = 0; j < 2; ++j) {
            const int idx = t + 256 * j;
            if (idx < NI * 64) {
                const int row = idx >> 2, c16 = idx & 3;
                const __half* src = g_mh + (size_t)(n0 + row) * 320 + ch * 32 + c16 * 8;
                const uint32_t off = swz((uint32_t)(row * 96 + c16 * 16), row);
                cp16(sb + BHo + off, src);
            }
        }
    };

    ldA(0); issueB(0, st(0)); cp_commit(); stA(st(0));
    ldA(1); issueB(1, st(1)); cp_commit(); stA(st(1));

    for (int ch = 0; ch < NC1; ++ch) {
        if (ch + 1 < NC1) cp_wait1(); else cp_wait0();
        __syncthreads();
        const int pf = ch + 2;
        if (pf < NC1) { issueB(pf, st(pf % 3)); cp_commit(); ldA(pf); }
        const uint32_t cur = st(ch % 3);
        compute_chunk<NI>(cur + AHo, cur + BHo, lane, wm, wn, c, 2);
        if (pf < NC1) stA(st(pf % 3));
    }

    // epilogue: fp32 accum -> proj fp16
#pragma unroll
    for (int mi = 0; mi < 2; ++mi)
#pragma unroll
    for (int ni = 0; ni < NI; ++ni) {
        const int r0   = m0 + wm * 32 + mi * 16 + (lane >> 2);
        const int colg = n0 + wn * (NI * 8) + ni * 8 + (lane & 3) * 2;
        *reinterpret_cast<uint32_t*>(g_ph + (size_t)r0 * PW + colg)
            = pack2(c[mi][ni][0], c[mi][ni][1]);
        *reinterpret_cast<uint32_t*>(g_ph + (size_t)(r0 + 8) * PW + colg)
            = pack2(c[mi][ni][2], c[mi][ni][3]);
    }
}

// ===========================================================================
// GEMM2 body: out[m-tile, v0..) = proj[m-tile,:208) . roles, col v==1 zeroed
// ===========================================================================
template<int NI>
DEVINL void gemm2_body(float* __restrict__ out,
                       uint32_t sb0, int m0, int v0, int b,
                       int t, int lane, int wm, int wn) {
    float c[2][NI][4] = {};
    const size_t rbase = (size_t)b * RV * RW;

    auto st = [&](int i) { return sb0 + (uint32_t)i * STAGE_B; };

    auto issue = [&](int ch, uint32_t sb) {
        const int k0 = ch * 32;
#pragma unroll
        for (int j = 0; j < 4; ++j) {
            const int idx = t + 256 * j;
            if (idx < 512) {                        // A: proj
                const int row = idx >> 2, c16 = idx & 3;
                const __half* src = g_ph + (size_t)(m0 + row) * PW + k0 + c16 * 8;
                const uint32_t off = swz((uint32_t)(row * 96 + c16 * 16), row);
                cp16(sb + AHo + off, src);
            } else if (idx < 512 + NI * 64) {       // B: roles
                const int i2 = idx - 512;
                const int row = i2 >> 2, c16 = i2 & 3;
                const __half* src = g_rh + rbase + (size_t)(v0 + row) * RW + k0 + c16 * 8;
                const uint32_t off = swz((uint32_t)(row * 96 + c16 * 16), row);
                cp16(sb + BHo + off, src);
            }
        }
    };

    issue(0, st(0)); cp_commit();
    issue(1, st(1)); cp_commit();

    for (int ch = 0; ch < NC2; ++ch) {
        if (ch + 1 < NC2) cp_wait1(); else cp_wait0();
        __syncthreads();
        const int pf = ch + 2;
        if (pf < NC2) { issue(pf, st(pf % 3)); cp_commit(); }
        const int scnt = (ch == NC2 - 1) ? 1 : 2;   // k 208..223 is all-zero pad
        const uint32_t cur = st(ch % 3);
        compute_chunk<NI>(cur + AHo, cur + BHo, lane, wm, wn, c, scnt);
    }

    // epilogue: fp32 stores, zero global column 1
#pragma unroll
    for (int mi = 0; mi < 2; ++mi)
#pragma unroll
    for (int ni = 0; ni < NI; ++ni) {
        const int r0   = m0 + wm * 32 + mi * 16 + (lane >> 2);
        const int colg = v0 + wn * (NI * 8) + ni * 8 + (lane & 3) * 2;
        if (colg < Vn) {
            float a0 = c[mi][ni][0], a1 = c[mi][ni][1];
            float a2 = c[mi][ni][2], a3 = c[mi][ni][3];
            if (colg == 0) { a1 = 0.f; a3 = 0.f; }
            *(float2*)(out + (size_t)r0 * Vn + colg)       = make_float2(a0, a1);
            *(float2*)(out + (size_t)(r0 + 8) * Vn + colg) = make_float2(a2, a3);
        }
    }
}

// ===========================================================================
// single launch: blocks [0,512) = gemm1, [512,1280) = gemm2 (per-tile flags)
// gemm1 indices all precede gemm2 indices -> producers dispatch first
// ===========================================================================
__global__ __launch_bounds__(256, 2) void gemms(
    const float* __restrict__ pre,
    const float* __restrict__ wid,
    float* __restrict__ out)
{
    extern __shared__ __align__(128) char smraw[];
    const uint32_t sb0 = smem_u32(smraw);
    const int t = threadIdx.x, lane = t & 31, warp = t >> 5;
    const int wm = warp >> 1, wn = warp & 1;

    if (blockIdx.x < G1_BLOCKS) {
        const int mt = blockIdx.x >> 1;
        const int m0 = mt * BM;
        if ((blockIdx.x & 1) == 0)
            gemm1_body<7>(pre, wid, sb0, m0, 0,   t, lane, wm, wn);   // cols 0..111
        else
            gemm1_body<6>(pre, wid, sb0, m0, 112, t, lane, wm, wn);   // cols 112..207
        // publish proj for this tile (threadFenceReduction pattern)
        __threadfence();
        __syncthreads();
        if (t == 0) atomicAdd(&g_flags[mt], 1);
    } else {
        const int j  = blockIdx.x - G1_BLOCKS;
        const int mt = j / 3, vt = j % 3;
        const int m0 = mt * BM;
        const int b  = mt >> 3;               // 8 m-tiles per batch
        if (t == 0) {
            while (ld_acquire(&g_flags[mt]) < 2) __nanosleep(64);
        }
        __syncthreads();
        if (vt < 2)
            gemm2_body<7>(out, sb0, m0, vt * 112, b, t, lane, wm, wn);
        else
            gemm2_body<5>(out, sb0, m0, 224, b, t, lane, wm, wn);   // v 224..303
    }
}

// ===========================================================================
// kernel_launch  (inputs: role_vectors, pretrained_emb, word_id_emb, matrix, seq_len)
// ===========================================================================
extern "C" void kernel_launch(void* const* d_in, const int* in_sizes, int n_in,
                              void* d_out, int out_size)
{
    const float* roles = (const float*)d_in[0];
    const float* pre   = (const float*)d_in[1];
    const float* wid   = (const float*)d_in[2];
    const float* mat   = (const float*)d_in[3];

    cudaFuncSetAttribute(gemms, cudaFuncAttributeMaxDynamicSharedMemorySize, SMEM_BYTES);

    prep_all<<<(PREP_TOTAL + 255) / 256, 256>>>(mat, roles);
    gemms<<<G1_BLOCKS + 3 * NTILE, 256, SMEM_BYTES>>>(pre, wid, (float*)d_out);
}